// round 8
// baseline (speedup 1.0000x reference)
#include <cuda_runtime.h>

// MatrixMemory (R8): direction-specialized CTAs, asymmetric tiling.
//   read blocks  (2 of 3): y = state @ query, 32 rows/block (4 rows/warp,
//                          8 front-batched LDG.128 per thread)
//   write blocks (1 of 3): dM = d_out ⊗ key, 64 rows/block (8 rows/warp,
//                          16 STG.128 per thread — long store bursts)
// Lane-contiguous 16B accesses throughout.

#define B_  2048
#define DK_ 256
#define DV_ 256

__global__ __launch_bounds__(256, 8)
void mm_split8_kernel(const float4* __restrict__ state,   // [B, DV, DK] as float4
                      const float4* __restrict__ query,   // [B, DK] as float4
                      const float4* __restrict__ keyv,    // [B, DK] as float4
                      const float*  __restrict__ dout,    // [B, DV]
                      float4*       __restrict__ y,       // [B, DV] as float4
                      float4*       __restrict__ dM)      // [B, DV, DK] as float4
{
    const int g = blockIdx.x / 3;
    const int r = blockIdx.x % 3;

    const int tid  = threadIdx.x;
    const int w    = tid >> 5;
    const int lane = tid & 31;

    if (r < 2) {
        // ---------------- READ stream: y = state @ query ----------------
        const int t  = g * 2 + r;              // 0..16383
        const int b  = t >> 3;                 // 8 tiles per batch
        const int rb = (t & 7) << 5;           // 32 rows per tile
        const long row0 = (long)b * DV_ + rb + w * 4;

        const float4* p = state + row0 * (DK_ / 4);

        float4 a[8];
        #pragma unroll
        for (int j = 0; j < 4; j++) {
            a[2*j]   = __ldcs(p + j * 64 + lane);
            a[2*j+1] = __ldcs(p + j * 64 + 32 + lane);
        }

        const float4 q0 = __ldg(query + b * 64 + lane);
        const float4 q1 = __ldg(query + b * 64 + 32 + lane);

        float yv[4];
        #pragma unroll
        for (int j = 0; j < 4; j++) {
            float s = a[2*j].x   * q0.x + a[2*j].y   * q0.y
                    + a[2*j].z   * q0.z + a[2*j].w   * q0.w
                    + a[2*j+1].x * q1.x + a[2*j+1].y * q1.y
                    + a[2*j+1].z * q1.z + a[2*j+1].w * q1.w;
            #pragma unroll
            for (int off = 16; off > 0; off >>= 1)
                s += __shfl_xor_sync(0xFFFFFFFFu, s, off);
            yv[j] = s;
        }
        if (lane == 0)
            y[row0 >> 2] = make_float4(yv[0], yv[1], yv[2], yv[3]);
    } else {
        // ---------------- WRITE stream: dM = d_out ⊗ key ----------------
        const int b  = g >> 2;                 // 4 tiles per batch
        const int rb = (g & 3) << 6;           // 64 rows per tile
        const long row0 = (long)b * DV_ + rb + w * 8;   // 8 rows per warp

        const float4 k0 = __ldg(keyv + b * 64 + lane);
        const float4 k1 = __ldg(keyv + b * 64 + 32 + lane);

        float dv[8];
        #pragma unroll
        for (int j = 0; j < 8; j++) dv[j] = __ldg(dout + row0 + j);

        float4* pd = dM + row0 * (DK_ / 4);
        #pragma unroll
        for (int j = 0; j < 8; j++) {
            const float d = dv[j];
            float4 o0 = make_float4(d * k0.x, d * k0.y, d * k0.z, d * k0.w);
            float4 o1 = make_float4(d * k1.x, d * k1.y, d * k1.z, d * k1.w);
            __stcs(pd + j * 64 + lane,      o0);
            __stcs(pd + j * 64 + 32 + lane, o1);
        }
    }
}

extern "C" void kernel_launch(void* const* d_in, const int* in_sizes, int n_in,
                              void* d_out, int out_size)
{
    const float4* state = (const float4*)d_in[0];
    const float4* query = (const float4*)d_in[1];
    const float4* keyv  = (const float4*)d_in[2];
    const float*  dov   = (const float*) d_in[3];

    float* out = (float*)d_out;
    float4* y  = (float4*)out;                     // [B, DV]
    float4* dM = (float4*)(out + (long)B_ * DV_);  // [B, DV, DK]

    // 8192 groups of 3 blocks: 2 read tiles (32 rows) + 1 write tile (64 rows)
    dim3 grid(8192 * 3);
    dim3 block(256);
    mm_split8_kernel<<<grid, block>>>(state, query, keyv, dov, y, dM);
}

// round 9
// speedup vs baseline: 1.0008x; 1.0008x over previous
#include <cuda_runtime.h>

// MatrixMemory (R9): direction-specialized CTAs, deep read-side MLP.
//   odd  blocks: y = state @ query — 128 thr, 4 warps x 8 rows/warp,
//                16 front-batched LDG.128 per thread.
//   even blocks: dM = d_out ⊗ key — 128 thr, 4 warps x 8 rows/warp,
//                16 STG.128 per thread.
// Lane-contiguous 16B accesses; vectors via __ldg (L2-resident).

#define B_  2048
#define DK_ 256
#define DV_ 256

__global__ __launch_bounds__(128, 5)
void mm_split9_kernel(const float4* __restrict__ state,   // [B, DV, DK] as float4
                      const float4* __restrict__ query,   // [B, DK] as float4
                      const float4* __restrict__ keyv,    // [B, DK] as float4
                      const float*  __restrict__ dout,    // [B, DV]
                      float4*       __restrict__ y,       // [B, DV] as float4
                      float4*       __restrict__ dM)      // [B, DV, DK] as float4
{
    const int t  = blockIdx.x >> 1;            // tile id 0..16383
    const int b  = t >> 3;                     // 8 tiles per batch
    const int rb = (t & 7) << 5;               // 32 rows per tile

    const int tid  = threadIdx.x;
    const int w    = tid >> 5;                 // 4 warps
    const int lane = tid & 31;
    const long row0 = (long)b * DV_ + rb + w * 8;   // 8 rows per warp

    if (blockIdx.x & 1) {
        // ---------------- READ stream: y = state @ query ----------------
        const float4* p = state + row0 * (DK_ / 4);

        // 16 independent front-batched streaming loads (8 rows x 2 x 16B)
        float4 a[16];
        #pragma unroll
        for (int j = 0; j < 8; j++) {
            a[2*j]   = __ldcs(p + j * 64 + lane);
            a[2*j+1] = __ldcs(p + j * 64 + 32 + lane);
        }

        const float4 q0 = __ldg(query + b * 64 + lane);
        const float4 q1 = __ldg(query + b * 64 + 32 + lane);

        float yv[8];
        #pragma unroll
        for (int j = 0; j < 8; j++) {
            float s = a[2*j].x   * q0.x + a[2*j].y   * q0.y
                    + a[2*j].z   * q0.z + a[2*j].w   * q0.w
                    + a[2*j+1].x * q1.x + a[2*j+1].y * q1.y
                    + a[2*j+1].z * q1.z + a[2*j+1].w * q1.w;
            #pragma unroll
            for (int off = 16; off > 0; off >>= 1)
                s += __shfl_xor_sync(0xFFFFFFFFu, s, off);
            yv[j] = s;                         // valid in lane 0
        }
        if (lane == 0) {
            y[(row0 >> 2)]     = make_float4(yv[0], yv[1], yv[2], yv[3]);
            y[(row0 >> 2) + 1] = make_float4(yv[4], yv[5], yv[6], yv[7]);
        }
    } else {
        // ---------------- WRITE stream: dM = d_out ⊗ key ----------------
        const float4 k0 = __ldg(keyv + b * 64 + lane);
        const float4 k1 = __ldg(keyv + b * 64 + 32 + lane);

        float dv[8];
        #pragma unroll
        for (int j = 0; j < 8; j++) dv[j] = __ldg(dout + row0 + j);

        float4* pd = dM + row0 * (DK_ / 4);
        #pragma unroll
        for (int j = 0; j < 8; j++) {
            const float d = dv[j];
            float4 o0 = make_float4(d * k0.x, d * k0.y, d * k0.z, d * k0.w);
            float4 o1 = make_float4(d * k1.x, d * k1.y, d * k1.z, d * k1.w);
            __stcs(pd + j * 64 + lane,      o0);
            __stcs(pd + j * 64 + 32 + lane, o1);
        }
    }
}

extern "C" void kernel_launch(void* const* d_in, const int* in_sizes, int n_in,
                              void* d_out, int out_size)
{
    const float4* state = (const float4*)d_in[0];
    const float4* query = (const float4*)d_in[1];
    const float4* keyv  = (const float4*)d_in[2];
    const float*  dov   = (const float*) d_in[3];

    float* out = (float*)d_out;
    float4* y  = (float4*)out;                     // [B, DV]
    float4* dM = (float4*)(out + (long)B_ * DV_);  // [B, DV, DK]

    // 16384 tiles x 2 directions, interleaved even(write)/odd(read)
    dim3 grid(B_ * 8 * 2);
    dim3 block(128);
    mm_split9_kernel<<<grid, block>>>(state, query, keyv, dov, y, dM);
}

// round 10
// speedup vs baseline: 1.0024x; 1.0016x over previous
#include <cuda_runtime.h>

// MatrixMemory (R10, final family): direction-specialized CTAs.
//   read blocks  (2 of 3): y = state @ query, 32 rows/block (8 warps x 4 rows,
//                          8 front-batched LDG.128 per thread)
//   write blocks (1 of 3): dM = d_out ⊗ key, 64 rows/block (8 warps x 8 rows,
//                          16 STG.128 per thread — long store bursts)
// Interleave pattern read-write-read keeps both HBM directions continuously
// balanced chip-wide. Lane-contiguous 16B accesses; .cs streaming hints;
// vectors via __ldg (1KB/batch, L2-resident, reused across tiles).
// Plateau analysis: ~6.8 TB/s = LTS cap on 50/50 mixed R/W stream (path-
// independent per B300 microarch); traffic is compulsory -> this is the floor.

#define B_  2048
#define DK_ 256
#define DV_ 256

__global__ __launch_bounds__(256, 8)
void mm_split10_kernel(const float4* __restrict__ state,   // [B, DV, DK] as float4
                       const float4* __restrict__ query,   // [B, DK] as float4
                       const float4* __restrict__ keyv,    // [B, DK] as float4
                       const float*  __restrict__ dout,    // [B, DV]
                       float4*       __restrict__ y,       // [B, DV] as float4
                       float4*       __restrict__ dM)      // [B, DV, DK] as float4
{
    const int g = blockIdx.x / 3;
    const int r = blockIdx.x % 3;          // 0: read, 1: write, 2: read

    const int tid  = threadIdx.x;
    const int w    = tid >> 5;
    const int lane = tid & 31;

    if (r != 1) {
        // ---------------- READ stream: y = state @ query ----------------
        const int t  = g * 2 + (r >> 1);       // 0..16383
        const int b  = t >> 3;                 // 8 tiles per batch
        const int rb = (t & 7) << 5;           // 32 rows per tile
        const long row0 = (long)b * DV_ + rb + w * 4;

        const float4* p = state + row0 * (DK_ / 4);

        float4 a[8];
        #pragma unroll
        for (int j = 0; j < 4; j++) {
            a[2*j]   = __ldcs(p + j * 64 + lane);
            a[2*j+1] = __ldcs(p + j * 64 + 32 + lane);
        }

        const float4 q0 = __ldg(query + b * 64 + lane);
        const float4 q1 = __ldg(query + b * 64 + 32 + lane);

        float yv[4];
        #pragma unroll
        for (int j = 0; j < 4; j++) {
            float s = a[2*j].x   * q0.x + a[2*j].y   * q0.y
                    + a[2*j].z   * q0.z + a[2*j].w   * q0.w
                    + a[2*j+1].x * q1.x + a[2*j+1].y * q1.y
                    + a[2*j+1].z * q1.z + a[2*j+1].w * q1.w;
            #pragma unroll
            for (int off = 16; off > 0; off >>= 1)
                s += __shfl_xor_sync(0xFFFFFFFFu, s, off);
            yv[j] = s;
        }
        if (lane == 0)
            y[row0 >> 2] = make_float4(yv[0], yv[1], yv[2], yv[3]);
    } else {
        // ---------------- WRITE stream: dM = d_out ⊗ key ----------------
        const int b  = g >> 2;                 // 4 tiles per batch
        const int rb = (g & 3) << 6;           // 64 rows per tile
        const long row0 = (long)b * DV_ + rb + w * 8;   // 8 rows per warp

        const float4 k0 = __ldg(keyv + b * 64 + lane);
        const float4 k1 = __ldg(keyv + b * 64 + 32 + lane);

        float dv[8];
        #pragma unroll
        for (int j = 0; j < 8; j++) dv[j] = __ldg(dout + row0 + j);

        float4* pd = dM + row0 * (DK_ / 4);
        #pragma unroll
        for (int j = 0; j < 8; j++) {
            const float d = dv[j];
            float4 o0 = make_float4(d * k0.x, d * k0.y, d * k0.z, d * k0.w);
            float4 o1 = make_float4(d * k1.x, d * k1.y, d * k1.z, d * k1.w);
            __stcs(pd + j * 64 + lane,      o0);
            __stcs(pd + j * 64 + 32 + lane, o1);
        }
    }
}

extern "C" void kernel_launch(void* const* d_in, const int* in_sizes, int n_in,
                              void* d_out, int out_size)
{
    const float4* state = (const float4*)d_in[0];
    const float4* query = (const float4*)d_in[1];
    const float4* keyv  = (const float4*)d_in[2];
    const float*  dov   = (const float*) d_in[3];

    float* out = (float*)d_out;
    float4* y  = (float4*)out;                     // [B, DV]
    float4* dM = (float4*)(out + (long)B_ * DV_);  // [B, DV, DK]

    // 8192 groups of 3 blocks: read tile, write tile, read tile
    dim3 grid(8192 * 3);
    dim3 block(256);
    mm_split10_kernel<<<grid, block>>>(state, query, keyv, dov, y, dM);
}